// round 1
// baseline (speedup 1.0000x reference)
#include <cuda_runtime.h>
#include <cstdint>

#define BB 4
#define TT 16
#define HH 64
#define WW 64
#define CIN 32
#define FF 64
#define GG 256   // 4*F gate channels

#define STATE_ELEMS (BB*HH*WW*FF)   // 1048576

// persistent state (no cudaMalloc allowed)
__device__ float g_h[2][STATE_ELEMS];
__device__ float g_c[STATE_ELEMS];

// ---------------- smem layout (dynamic) ----------------
// [0      , 66560): union { As[32][65] @0 ; Bs[32][256] @8448 } | zs[64][260]
// [66560  , 75008): xc[64][33]
// [75008  , 83200): wpsm[32][64]
// [83200  , 84224): bsm[256]
#define SMEM_BYTES 84224
#define OFF_BS   8448
#define OFF_XC   66560
#define OFF_WP   75008
#define OFF_BSM  83200

__global__ void init_state_kernel() {
    int stride = gridDim.x * blockDim.x;
    for (int i = blockIdx.x * blockDim.x + threadIdx.x; i < STATE_ELEMS; i += stride) {
        g_h[0][i] = 0.0f;
        g_c[i]    = 0.0f;
    }
}

__global__ void step_kernel(const float* __restrict__ x,
                            const float* __restrict__ Wx,
                            const float* __restrict__ Wh,
                            const float* __restrict__ bias,
                            const float* __restrict__ Wp,
                            const float* __restrict__ bp,
                            float* __restrict__ out,
                            int t)
{
    extern __shared__ char smem_raw[];
    float* As   = (float*)(smem_raw);             // [32][65]
    float* Bs   = (float*)(smem_raw + OFF_BS);    // [32][256]
    float* zs   = (float*)(smem_raw);             // [64][260] (aliases As/Bs)
    float* xc   = (float*)(smem_raw + OFF_XC);    // [64][33]
    float* wpsm = (float*)(smem_raw + OFF_WP);    // [32][64]
    float* bsm  = (float*)(smem_raw + OFF_BSM);   // [256]

    const int tid  = threadIdx.x;
    const int b    = blockIdx.y;
    const int tile = blockIdx.x;
    const int y0 = (tile >> 3) * 8;
    const int x0 = (tile & 7) * 8;

    const float* __restrict__ hprev = g_h[t & 1];
    float*       __restrict__ hnew  = g_h[(t + 1) & 1];

    // ---- preload x center tile, Wp, bias ----
    {
        const int c  = tid & 31;
        const int p0 = tid >> 5;
        const float* xb = x + ((size_t)(b * TT + t) * HH * WW) * CIN;
        for (int p = p0; p < 64; p += 8) {
            int py = p >> 3, pxl = p & 7;
            xc[p * 33 + c] = xb[((y0 + py) * WW + (x0 + pxl)) * CIN + c];
        }
        for (int i = tid; i < 32 * 64; i += 256) wpsm[i] = Wp[i];
        bsm[tid] = bias[tid];
    }

    // ---- thread tiling for the implicit GEMM ----
    // CTA: 64 px x 256 gates. warp -> (ngroup in {0,128}, 16-px group);
    // lane -> lr(0..3)*4 px, lc(0..7)*2-ch pairs strided by 16.
    const int warp = tid >> 5, lane = tid & 31;
    const int ng   = (warp >> 2) * 128;
    const int pxg  = (warp & 3) * 16;
    const int lr   = lane >> 3, lc = lane & 7;
    const int prow = pxg + lr * 4;
    const int chb  = ng + lc * 2;

    unsigned long long acc[4][8];
#pragma unroll
    for (int i = 0; i < 4; i++)
#pragma unroll
        for (int j = 0; j < 8; j++) acc[i][j] = 0ull;

    // ---- main loop: K = 9 taps x 3 channel-chunks of 32 ----
    for (int kc = 0; kc < 27; kc++) {
        const int tap  = kc / 3;
        const int srcp = kc - tap * 3;        // 0: x ch0-31, 1: h ch0-31, 2: h ch32-63
        const int dy = tap / 3, dx = tap % 3;

        __syncthreads();
        // load A tile (64 px x 32 ch, with halo + zero padding), As[c][p]
        {
            const int c  = tid & 31;
            const int p0 = tid >> 5;
            for (int p = p0; p < 64; p += 8) {
                int py = p >> 3, pxl = p & 7;
                int gy = y0 + py + dy - 1;
                int gx = x0 + pxl + dx - 1;
                float v = 0.0f;
                if ((unsigned)gy < HH && (unsigned)gx < WW) {
                    if (srcp == 0)
                        v = x[(((size_t)(b * TT + t) * HH + gy) * WW + gx) * CIN + c];
                    else
                        v = hprev[((size_t)(b * HH + gy) * WW + gx) * FF + (srcp - 1) * 32 + c];
                }
                As[c * 65 + p] = v;
            }
        }
        // load B tile (32 ch x 256 gates), Bs[c][g]
        {
            const float* wsrc;
            int cinw, cbase;
            if (srcp == 0) { wsrc = Wx; cinw = 32; cbase = 0; }
            else           { wsrc = Wh; cinw = 64; cbase = (srcp - 1) * 32; }
            for (int idx = tid; idx < 2048; idx += 256) {
                int c  = idx >> 6;
                int g4 = (idx & 63) << 2;
                float4 v = *(const float4*)&wsrc[((size_t)(tap * cinw + cbase + c)) * GG + g4];
                *(float4*)&Bs[c * 256 + g4] = v;
            }
        }
        __syncthreads();

#pragma unroll 2
        for (int k = 0; k < 32; k++) {
            unsigned long long a2[4], b2[8];
#pragma unroll
            for (int i = 0; i < 4; i++) {
                float a = As[k * 65 + prow + i];
                asm("mov.b64 %0, {%1, %1};" : "=l"(a2[i]) : "f"(a));
            }
#pragma unroll
            for (int j = 0; j < 8; j++)
                b2[j] = *(const unsigned long long*)&Bs[k * 256 + chb + 16 * j];
#pragma unroll
            for (int i = 0; i < 4; i++)
#pragma unroll
                for (int j = 0; j < 8; j++)
                    asm("fma.rn.f32x2 %0, %1, %2, %0;"
                        : "+l"(acc[i][j]) : "l"(a2[i]), "l"(b2[j]));
        }
    }

    // ---- stage z into smem for gate-wise epilogue ----
    __syncthreads();
#pragma unroll
    for (int i = 0; i < 4; i++)
#pragma unroll
        for (int j = 0; j < 8; j++)
            *(unsigned long long*)&zs[(prow + i) * 260 + chb + 16 * j] = acc[i][j];
    __syncthreads();

    // ---- epilogue: gates + state update + residual 1x1 + output ----
    {
        const int g     = tid & 63;
        const int pbase = (tid >> 6) * 16;

        float wreg[32];
#pragma unroll
        for (int ci = 0; ci < 32; ci++) wreg[ci] = wpsm[ci * 64 + g];
        const float bi = bsm[g], bf = bsm[64 + g], bc = bsm[128 + g], bo = bsm[192 + g];
        const float bpv = bp[g];

        for (int ii = 0; ii < 16; ii++) {
            int p  = pbase + ii;
            int py = p >> 3, pxl = p & 7;
            float zi = zs[p * 260 + g]       + bi;
            float zf = zs[p * 260 + 64 + g]  + bf;
            float zc = zs[p * 260 + 128 + g] + bc;
            float zo = zs[p * 260 + 192 + g] + bo;
            float ig = __saturatef(0.2f * zi + 0.5f);
            float fg = __saturatef(0.2f * zf + 0.5f);
            float og = __saturatef(0.2f * zo + 0.5f);

            size_t sidx = ((size_t)(b * HH + (y0 + py)) * WW + (x0 + pxl)) * FF + g;
            float cold = g_c[sidx];
            float cnew = fg * cold + ig * tanhf(zc);
            float hn   = og * tanhf(cnew);
            g_c[sidx]  = cnew;
            hnew[sidx] = hn;

            float res = bpv;
#pragma unroll
            for (int ci = 0; ci < 32; ci++) res += xc[p * 33 + ci] * wreg[ci];

            out[(((size_t)(b * TT + t) * HH + (y0 + py)) * WW + (x0 + pxl)) * FF + g] = hn + res;
        }
    }
}

extern "C" void kernel_launch(void* const* d_in, const int* in_sizes, int n_in,
                              void* d_out, int out_size)
{
    const float* x    = (const float*)d_in[0];
    const float* Wx   = (const float*)d_in[1];
    const float* Wh   = (const float*)d_in[2];
    const float* bias = (const float*)d_in[3];
    const float* Wp   = (const float*)d_in[4];
    const float* bp   = (const float*)d_in[5];
    float* out = (float*)d_out;

    cudaFuncSetAttribute(step_kernel, cudaFuncAttributeMaxDynamicSharedMemorySize, SMEM_BYTES);

    init_state_kernel<<<1024, 256>>>();

    dim3 grid(64, BB);   // 64 spatial tiles (8x8 of 8x8 px) x batch
    for (int t = 0; t < TT; t++)
        step_kernel<<<grid, 256, SMEM_BYTES>>>(x, Wx, Wh, bias, Wp, bp, out, t);
}

// round 3
// speedup vs baseline: 1.3625x; 1.3625x over previous
#include <cuda_runtime.h>
#include <cstdint>

#define BB 4
#define TT 16
#define HH 64
#define WW 64
#define CIN 32
#define FF 64
#define GG 256   // 4*F gate channels

#define STATE_ELEMS (BB*HH*WW*FF)   // 1048576

// persistent state (no cudaMalloc allowed)
__device__ float g_h[2][STATE_ELEMS];
__device__ float g_c[STATE_ELEMS];

// ---------------- smem layout (bytes) ----------------
// As[2][128][36]  : 0      .. 36864
// Bs[2][32][256]  : 36864  .. 102400
// zs[128][260]    : 0      .. 133120   (aliases As+Bs after main loop)
// xc[128][32]     : 133120 .. 149504
// wpsm[32][64]    : 149504 .. 157696
// bsm[256]        : 157696 .. 158720
// bpsm[64]        : 158720 .. 158976
#define A_BUF_BYTES 18432
#define OFF_B   36864
#define B_BUF_BYTES 32768
#define OFF_XC  133120
#define OFF_WP  149504
#define OFF_BSM 157696
#define OFF_BPS 158720
#define SMEM_BYTES 158976

__global__ void init_state_kernel() {
    int stride = gridDim.x * blockDim.x;
    for (int i = blockIdx.x * blockDim.x + threadIdx.x; i < STATE_ELEMS; i += stride) {
        g_h[0][i] = 0.0f;
        g_c[i]    = 0.0f;
    }
}

__device__ __forceinline__ void cp16(void* dst, const void* src, int sz) {
    unsigned d = (unsigned)__cvta_generic_to_shared(dst);
    asm volatile("cp.async.cg.shared.global [%0], [%1], 16, %2;\n"
                 :: "r"(d), "l"(src), "r"(sz));
}
__device__ __forceinline__ void cp_commit() {
    asm volatile("cp.async.commit_group;\n" ::: "memory");
}
__device__ __forceinline__ void cp_wait0() {
    asm volatile("cp.async.wait_group 0;\n" ::: "memory");
}

// issue global->smem loads for K-chunk kc into buffer s
__device__ __forceinline__ void issue_loads(
    int kc, int s, char* smem,
    const float* __restrict__ x, const float* __restrict__ Wx,
    const float* __restrict__ Wh, const float* __restrict__ hprev,
    int b, int tstep, int ty0, int tx0, int tid)
{
    const int tap  = kc / 3;
    const int srcp = kc - tap * 3;       // 0: x ch0-31, 1: h ch0-31, 2: h ch32-63
    const int dy = tap / 3 - 1, dx = tap % 3 - 1;

    float* As = (float*)(smem + s * A_BUF_BYTES);
    float* Bs = (float*)(smem + OFF_B + s * B_BUF_BYTES);

    // ---- A tile: 128 px x 32 ch, As[p][36] ----
    {
        const int p = tid >> 2, q = tid & 3;
        const int py = p >> 3, pxl = p & 7;
        const int gy = ty0 + py + dy, gx = tx0 + pxl + dx;
        const bool ok = ((unsigned)gy < (unsigned)HH) && ((unsigned)gx < (unsigned)WW);
        const int cy = ok ? gy : 0, cx = ok ? gx : 0;
        const int sz = ok ? 16 : 0;
        const float* src;
        if (srcp == 0)
            src = x + (((size_t)(b * TT + tstep) * HH + cy) * WW + cx) * CIN;
        else
            src = hprev + (((size_t)b * HH + cy) * WW + cx) * FF + (srcp - 1) * 32;
        float* dstrow = As + p * 36;
#pragma unroll
        for (int h = 0; h < 2; h++) {
            int c = 8 * q + 4 * h;
            cp16(dstrow + c, src + c, sz);
        }
    }

    // ---- B tile: 32 ch x 256 gates, Bs[c][256] ----
    {
        const float* wsrc;
        int cinw, cbase;
        if (srcp == 0) { wsrc = Wx; cinw = 32; cbase = 0; }
        else           { wsrc = Wh; cinw = 64; cbase = (srcp - 1) * 32; }
#pragma unroll
        for (int r = 0; r < 4; r++) {
            int idx = tid + 512 * r;
            int c = idx >> 6, q4 = (idx & 63) << 2;
            cp16(Bs + c * 256 + q4,
                 wsrc + ((size_t)(tap * cinw + cbase + c)) * GG + q4, 16);
        }
    }
}

__device__ __forceinline__ void compute_chunk(
    const float* __restrict__ As, const float* __restrict__ Bs,
    unsigned long long acc[4][8], int prow0, int chb)
{
#pragma unroll 2
    for (int k = 0; k < 32; k++) {
        unsigned long long a2[4], b2[8];
#pragma unroll
        for (int i = 0; i < 4; i++) {
            float a = As[(prow0 + 4 * i) * 36 + k];
            asm("mov.b64 %0, {%1, %1};" : "=l"(a2[i]) : "f"(a));
        }
#pragma unroll
        for (int j = 0; j < 8; j++)
            b2[j] = *(const unsigned long long*)(Bs + k * 256 + chb + 16 * j);
#pragma unroll
        for (int i = 0; i < 4; i++)
#pragma unroll
            for (int j = 0; j < 8; j++)
                asm("fma.rn.f32x2 %0, %1, %2, %0;"
                    : "+l"(acc[i][j]) : "l"(a2[i]), "l"(b2[j]));
    }
}

__global__ void __launch_bounds__(512, 1)
step_kernel(const float* __restrict__ x,
            const float* __restrict__ Wx,
            const float* __restrict__ Wh,
            const float* __restrict__ bias,
            const float* __restrict__ Wp,
            const float* __restrict__ bp,
            float* __restrict__ out,
            int tstep)
{
    extern __shared__ char smem[];
    float* zs   = (float*)(smem);              // [128][260], aliases A/B bufs
    float* xc   = (float*)(smem + OFF_XC);     // [128][32]
    float* wpsm = (float*)(smem + OFF_WP);     // [32][64]
    float* bsm  = (float*)(smem + OFF_BSM);    // [256]
    float* bpsm = (float*)(smem + OFF_BPS);    // [64]

    const int tid  = threadIdx.x;
    const int b    = blockIdx.y;
    const int tile = blockIdx.x;               // 0..31
    const int ty0 = (tile >> 3) * 16;
    const int tx0 = (tile & 7) * 8;

    const float* __restrict__ hprev = g_h[tstep & 1];
    float*       __restrict__ hnew  = g_h[(tstep + 1) & 1];

    // ---- preload x center tile (for residual), Wp, biases ----
    {
        const int p = tid >> 2, q = tid & 3;
        const int py = p >> 3, pxl = p & 7;
        const float* src = x + (((size_t)(b * TT + tstep) * HH + ty0 + py) * WW + tx0 + pxl) * CIN;
#pragma unroll
        for (int h = 0; h < 2; h++) {
            int c = 8 * q + 4 * h;
            *(float4*)(xc + p * 32 + c) = *(const float4*)(src + c);
        }
        for (int i = tid; i < 32 * 64; i += 512) wpsm[i] = Wp[i];
        if (tid < 256) bsm[tid] = bias[tid];
        if (tid < 64)  bpsm[tid] = bp[tid];
    }

    // ---- thread tiling: 128 px x 256 gates / 512 threads ----
    const int warp = tid >> 5, lane = tid & 31;
    const int pxg = (warp >> 1) * 16;
    const int ng  = (warp & 1) * 128;
    const int lr  = lane >> 3, lc = lane & 7;
    const int prow0 = pxg + lr;          // rows prow0 + 4*i
    const int chb   = ng + lc * 2;       // cols chb + 16*j (pairs)

    unsigned long long acc[4][8];
#pragma unroll
    for (int i = 0; i < 4; i++)
#pragma unroll
        for (int j = 0; j < 8; j++) acc[i][j] = 0ull;

    // ---- software-pipelined main loop over K = 27 chunks of 32 ----
    issue_loads(0, 0, smem, x, Wx, Wh, hprev, b, tstep, ty0, tx0, tid);
    cp_commit();

    for (int kc = 0; kc < 27; kc++) {
        cp_wait0();
        __syncthreads();
        if (kc < 26) {
            issue_loads(kc + 1, (kc + 1) & 1, smem, x, Wx, Wh, hprev, b, tstep, ty0, tx0, tid);
            cp_commit();
        }
        const float* As = (const float*)(smem + (kc & 1) * A_BUF_BYTES);
        const float* Bs = (const float*)(smem + OFF_B + (kc & 1) * B_BUF_BYTES);
        compute_chunk(As, Bs, acc, prow0, chb);
    }

    // ---- stage z into smem (aliases A/B buffers) ----
    __syncthreads();
#pragma unroll
    for (int i = 0; i < 4; i++)
#pragma unroll
        for (int j = 0; j < 8; j++)
            *(unsigned long long*)(zs + (prow0 + 4 * i) * 260 + chb + 16 * j) = acc[i][j];
    __syncthreads();

    // ---- epilogue: gates + state update + residual 1x1 + output ----
    {
        const int g  = tid & 63;
        const int pg = tid >> 6;           // 0..7
        const float bi = bsm[g], bf = bsm[64 + g], bc = bsm[128 + g], bo = bsm[192 + g];
        const float bpv = bpsm[g];

        for (int ii = 0; ii < 16; ii++) {
            int p  = pg * 16 + ii;
            int py = p >> 3, pxl = p & 7;
            float zi = zs[p * 260 + g]       + bi;
            float zf = zs[p * 260 + 64 + g]  + bf;
            float zc = zs[p * 260 + 128 + g] + bc;
            float zo = zs[p * 260 + 192 + g] + bo;
            float ig = __saturatef(0.2f * zi + 0.5f);
            float fg = __saturatef(0.2f * zf + 0.5f);
            float og = __saturatef(0.2f * zo + 0.5f);

            size_t sidx = ((size_t)(b * HH + (ty0 + py)) * WW + (tx0 + pxl)) * FF + g;
            float cold = g_c[sidx];
            float cnew = fg * cold + ig * tanhf(zc);
            float hn   = og * tanhf(cnew);
            g_c[sidx]  = cnew;
            hnew[sidx] = hn;

            float res = bpv;
#pragma unroll
            for (int ci = 0; ci < 32; ci++) res += xc[p * 32 + ci] * wpsm[ci * 64 + g];

            out[(((size_t)(b * TT + tstep) * HH + (ty0 + py)) * WW + (tx0 + pxl)) * FF + g] = hn + res;
        }
    }
}

extern "C" void kernel_launch(void* const* d_in, const int* in_sizes, int n_in,
                              void* d_out, int out_size)
{
    const float* x    = (const float*)d_in[0];
    const float* Wx   = (const float*)d_in[1];
    const float* Wh   = (const float*)d_in[2];
    const float* bias = (const float*)d_in[3];
    const float* Wp   = (const float*)d_in[4];
    const float* bp   = (const float*)d_in[5];
    float* out = (float*)d_out;

    cudaFuncSetAttribute(step_kernel, cudaFuncAttributeMaxDynamicSharedMemorySize, SMEM_BYTES);

    init_state_kernel<<<1024, 256>>>();

    dim3 grid(32, BB);   // 32 spatial tiles (16x8 px) x batch = 128 CTAs
    for (int t = 0; t < TT; t++)
        step_kernel<<<grid, 512, SMEM_BYTES>>>(x, Wx, Wh, bias, Wp, bp, out, t);
}

// round 9
// speedup vs baseline: 3.0270x; 2.2217x over previous
#include <cuda_runtime.h>
#include <cuda_bf16.h>
#include <cstdint>

#define BB 4
#define TT 16
#define HH 64
#define WW 64
#define CIN 32
#define FF 64
#define GG 256

#define STATE_ELEMS (BB*HH*WW*FF)

// persistent scratch (no cudaMalloc allowed)
__device__ float g_c[STATE_ELEMS];
__device__ unsigned char g_hsplit[2][BB*HH*WW*256];          // per px: hi(0-31)|lo(0-31)|hi(32-63)|lo(32-63)
__device__ unsigned char g_xsplit[(size_t)BB*TT*HH*WW*128];  // per px: hi(0-31)|lo(0-31)
__device__ unsigned char g_Bpack[27*32768];                  // pre-swizzled bf16 B images per K-chunk

// ---------------- smem layout (bytes) ----------------
// A ring [2][128 rows x 128B]  : 0      .. 32768
// B ring [2][256 rows x 128B]  : 32768  .. 98304
// zs[128][260] f32 aliases rings after mainloop: 0 .. 133120
#define OFF_A    0
#define A_STG    16384
#define OFF_B    32768
#define B_STG    32768
#define OFF_BSM  133120   // bias 256 f
#define OFF_BPS  134144   // bp 64 f
#define OFF_XC   134400   // xc[128][32] f32 (128B/px)
#define OFF_WP   150784   // wpsm[32][64] f32
#define SMEM_BYTES 158976
#define ZS_STRIDE 260

__device__ __forceinline__ unsigned swz(unsigned off) { return off ^ ((off >> 3) & 0x70); }

__device__ __forceinline__ void cp16(unsigned dsh, const void* src, int sz) {
    asm volatile("cp.async.cg.shared.global [%0], [%1], 16, %2;" :: "r"(dsh), "l"(src), "r"(sz));
}
__device__ __forceinline__ void cp_commit() { asm volatile("cp.async.commit_group;" ::: "memory"); }
__device__ __forceinline__ void cp_wait1() { asm volatile("cp.async.wait_group 1;" ::: "memory"); }
__device__ __forceinline__ void cp_wait0() { asm volatile("cp.async.wait_group 0;" ::: "memory"); }

#define LDSM4(d, addr) \
    asm volatile("ldmatrix.sync.aligned.m8n8.x4.shared.b16 {%0,%1,%2,%3}, [%4];" \
                 : "=r"((d)[0]), "=r"((d)[1]), "=r"((d)[2]), "=r"((d)[3]) : "r"(addr))

#define MMA16816(c, a, b0, b1) \
    asm volatile("mma.sync.aligned.m16n8k16.row.col.f32.bf16.bf16.f32 " \
                 "{%0,%1,%2,%3}, {%4,%5,%6,%7}, {%8,%9}, {%0,%1,%2,%3};" \
                 : "+f"((c)[0]), "+f"((c)[1]), "+f"((c)[2]), "+f"((c)[3]) \
                 : "r"((a)[0]), "r"((a)[1]), "r"((a)[2]), "r"((a)[3]), "r"(b0), "r"(b1))

// ---------------- prep kernels ----------------
__global__ void init_state_kernel() {
    int stride = gridDim.x * blockDim.x;
    for (int i = blockIdx.x * blockDim.x + threadIdx.x; i < STATE_ELEMS; i += stride)
        g_c[i] = 0.0f;
    uint4 z = make_uint4(0, 0, 0, 0);
    uint4* hs = (uint4*)g_hsplit[0];
    for (int i = blockIdx.x * blockDim.x + threadIdx.x; i < (BB*HH*WW*256)/16; i += stride)
        hs[i] = z;
}

__global__ void prep_weights_kernel(const float* __restrict__ Wx,
                                    const float* __restrict__ Wh) {
    int idx = blockIdx.x * blockDim.x + threadIdx.x;
    if (idx >= 27 * 16384) return;
    int kc = idx >> 14;
    int r  = idx & 16383;
    int n  = r >> 6;
    int k  = r & 63;
    int tap = kc / 3, srcp = kc - tap * 3;
    int ch = k & 31;
    bool lo = k >= 32;
    float w = (srcp == 0) ? Wx[(tap * 32 + ch) * GG + n]
                          : Wh[(tap * 64 + (srcp - 1) * 32 + ch) * GG + n];
    __nv_bfloat16 hb = __float2bfloat16(w);
    __nv_bfloat16 v  = lo ? __float2bfloat16(w - __bfloat162float(hb)) : hb;
    unsigned off = (unsigned)kc * 32768u + swz((unsigned)(n * 128 + k * 2));
    *(unsigned short*)(g_Bpack + off) = *(unsigned short*)&v;
}

__global__ void convx_kernel(const float* __restrict__ x) {
    size_t idx = (size_t)blockIdx.x * blockDim.x + threadIdx.x;  // 4194304 total
    int cp2 = (int)(idx & 15);
    size_t pix = idx >> 4;
    float2 v = *(const float2*)(x + pix * 32 + cp2 * 2);
    __nv_bfloat16 h0 = __float2bfloat16(v.x), h1 = __float2bfloat16(v.y);
    __nv_bfloat16 l0 = __float2bfloat16(v.x - __bfloat162float(h0));
    __nv_bfloat16 l1 = __float2bfloat16(v.y - __bfloat162float(h1));
    unsigned hp = ((unsigned)*(unsigned short*)&h1 << 16) | *(unsigned short*)&h0;
    unsigned lp = ((unsigned)*(unsigned short*)&l1 << 16) | *(unsigned short*)&l0;
    *(unsigned*)(g_xsplit + pix * 128 + cp2 * 4) = hp;
    *(unsigned*)(g_xsplit + pix * 128 + 64 + cp2 * 4) = lp;
}

// ---------------- producer: pure cp.async for chunk kc ----------------
__device__ __forceinline__ void produce(int kc, uint32_t su,
                                        const unsigned char* __restrict__ hsp,
                                        int b, int tstep, int ty0, int tx0, int tid) {
    const int s = kc & 1;
    const int row = tid >> 1, half = tid & 1;
    const int py = row >> 3, px = row & 7;
    const int tap = kc / 3, srcp = kc - tap * 3;
    const int gy = ty0 + py + tap / 3 - 1;
    const int gx = tx0 + px + (tap % 3) - 1;
    const bool ok = ((unsigned)gy < HH) && ((unsigned)gx < WW);
    const int cy = ok ? gy : 0, cx = ok ? gx : 0;
    const int sz = ok ? 16 : 0;
    const unsigned char* src;
    if (srcp == 0)
        src = g_xsplit + (((size_t)(b * TT + tstep) * HH + cy) * WW + cx) * 128 + half * 64;
    else
        src = hsp + (((size_t)b * HH + cy) * WW + cx) * 256 + (srcp - 1) * 128 + half * 64;
    unsigned Ab = su + OFF_A + s * A_STG;
    unsigned base = (unsigned)(row * 128 + half * 64);
#pragma unroll
    for (int q = 0; q < 4; q++)
        cp16(Ab + swz(base + q * 16), src + q * 16, sz);

    const unsigned char* bsrc = g_Bpack + (size_t)kc * 32768;
    unsigned Bb = su + OFF_B + s * B_STG;
#pragma unroll
    for (int r2 = 0; r2 < 8; r2++) {
        int o = (tid + 256 * r2) * 16;
        cp16(Bb + o, bsrc + o, 16);
    }
    cp_commit();
}

// ---------------- main step kernel ----------------
__global__ void __launch_bounds__(256, 1)
step_kernel(const float* __restrict__ x,
            const float* __restrict__ bias,
            const float* __restrict__ Wp,
            const float* __restrict__ bp,
            float* __restrict__ out,
            int tstep) {
    extern __shared__ char smem[];
    const uint32_t su = (uint32_t)__cvta_generic_to_shared(smem);
    const int tid  = threadIdx.x;
    const int b    = blockIdx.y;
    const int tile = blockIdx.x;
    const int ty0 = (tile >> 3) * 16;
    const int tx0 = (tile & 7) * 8;
    const int warp = tid >> 5, lane = tid & 31;

    const unsigned char* hsp = g_hsplit[tstep & 1];

    // ---- preload xc (cp.async, joins chunk0's group), Wp, bias ----
    {
        const int p = tid >> 1, half = tid & 1;
        const int py = p >> 3, pxl = p & 7;
        const float* src = x + (((size_t)(b * TT + tstep) * HH + ty0 + py) * WW + tx0 + pxl) * CIN + half * 16;
        unsigned dst = su + OFF_XC + (unsigned)(p * 128 + half * 64);
#pragma unroll
        for (int q = 0; q < 4; q++)
            cp16(dst + q * 16, src + q * 4, 16);

        float* wpsm = (float*)(smem + OFF_WP);
        for (int i = tid; i < 32 * 64; i += 256) wpsm[i] = Wp[i];
        ((float*)(smem + OFF_BSM))[tid] = bias[tid];
        if (tid < 64) ((float*)(smem + OFF_BPS))[tid] = bp[tid];
    }

    // ---- warp/thread MMA tiling ----
    const int mw = warp >> 2, nw = warp & 3;   // warp tile: rows mw*64, cols nw*64
    const int r8 = lane & 7, q = lane >> 3;
    int arow[4], axm[4];
#pragma unroll
    for (int mt = 0; mt < 4; mt++) {
        int rw = mw * 64 + mt * 16 + (q & 1) * 8 + r8;
        arow[mt] = rw * 128;
        axm[mt]  = (rw & 7) << 4;
    }
    const int akq = (q >> 1) * 16;
    int brow[4], bxm[4];
#pragma unroll
    for (int bt = 0; bt < 4; bt++) {
        int rw = nw * 64 + bt * 16 + (q >> 1) * 8 + r8;
        brow[bt] = rw * 128;
        bxm[bt]  = (rw & 7) << 4;
    }
    const int bkq = (q & 1) * 16;

    float c[4][8][4];
#pragma unroll
    for (int i = 0; i < 4; i++)
#pragma unroll
        for (int j = 0; j < 8; j++)
#pragma unroll
            for (int e = 0; e < 4; e++) c[i][j][e] = 0.0f;

    // ---- pipelined main loop: 27 chunks, 2-stage ----
    produce(0, su, hsp, b, tstep, ty0, tx0, tid);
    produce(1, su, hsp, b, tstep, ty0, tx0, tid);

    const int APO[3] = {0, 0, 64};   // hi.hi, hi.lo, lo.hi
    const int BPO[3] = {0, 64, 0};

    for (int kc = 0; kc < 27; kc++) {
        if (kc < 26) cp_wait1(); else cp_wait0();
        __syncthreads();

        const unsigned Ab = su + OFF_A + (kc & 1) * A_STG;
        const unsigned Bb = su + OFF_B + (kc & 1) * B_STG;
#pragma unroll
        for (int pass = 0; pass < 3; pass++) {
#pragma unroll
            for (int j = 0; j < 2; j++) {
                const int ac = APO[pass] + j * 32 + akq;
                const int bc = BPO[pass] + j * 32 + bkq;
                unsigned a[4][4];
#pragma unroll
                for (int mt = 0; mt < 4; mt++)
                    LDSM4(a[mt], Ab + arow[mt] + (ac ^ axm[mt]));
#pragma unroll
                for (int bt = 0; bt < 4; bt++) {
                    unsigned bb[4];
                    LDSM4(bb, Bb + brow[bt] + (bc ^ bxm[bt]));
#pragma unroll
                    for (int mt = 0; mt < 4; mt++) {
                        MMA16816(c[mt][2 * bt],     a[mt], bb[0], bb[1]);
                        MMA16816(c[mt][2 * bt + 1], a[mt], bb[2], bb[3]);
                    }
                }
            }
        }
        __syncthreads();
        if (kc + 2 <= 26) produce(kc + 2, su, hsp, b, tstep, ty0, tx0, tid);
    }

    // all warps done reading A/B rings before zs aliases them
    __syncthreads();

    // ---- stage z into smem zs[128][260] (aliases A/B rings) ----
    {
        float* zsm = (float*)smem;
#pragma unroll
        for (int mt = 0; mt < 4; mt++) {
            int m0 = mw * 64 + mt * 16 + (lane >> 2);
#pragma unroll
            for (int nt = 0; nt < 8; nt++) {
                int n0 = nw * 64 + nt * 8 + (lane & 3) * 2;
                *(float2*)&zsm[m0 * ZS_STRIDE + n0]       = make_float2(c[mt][nt][0], c[mt][nt][1]);
                *(float2*)&zsm[(m0 + 8) * ZS_STRIDE + n0] = make_float2(c[mt][nt][2], c[mt][nt][3]);
            }
        }
    }
    __syncthreads();

    // ---- epilogue: gates + state + residual 1x1 + output ----
    {
        const float* zsm  = (const float*)smem;
        const float* bsm  = (const float*)(smem + OFF_BSM);
        const float* bps  = (const float*)(smem + OFF_BPS);
        const float* xc   = (const float*)(smem + OFF_XC);
        const float* wpsm = (const float*)(smem + OFF_WP);
        const int g  = tid & 63;
        const int pg = tid >> 6;          // 0..3, 32 px each
        const float bi = bsm[g], bf = bsm[64 + g], bc = bsm[128 + g], bo = bsm[192 + g];
        const float bpv = bps[g];
        unsigned char* hs = g_hsplit[(tstep + 1) & 1];

        float wreg[32];
#pragma unroll
        for (int ci = 0; ci < 32; ci++) wreg[ci] = wpsm[ci * 64 + g];

        for (int ii = 0; ii < 32; ii++) {
            int p  = pg * 32 + ii;
            int py = p >> 3, pxl = p & 7;
            const float* zr = zsm + p * ZS_STRIDE;
            float zi = zr[g] + bi;
            float zf = zr[64 + g] + bf;
            float zc = zr[128 + g] + bc;
            float zo = zr[192 + g] + bo;
            float ig = __saturatef(0.2f * zi + 0.5f);
            float fg = __saturatef(0.2f * zf + 0.5f);
            float og = __saturatef(0.2f * zo + 0.5f);

            size_t sidx = ((size_t)(b * HH + (ty0 + py)) * WW + (tx0 + pxl)) * FF + g;
            float cold = g_c[sidx];
            float cnew = fg * cold + ig * tanhf(zc);
            float hn   = og * tanhf(cnew);
            g_c[sidx]  = cnew;

            // write split-bf16 h for next step's MMA
            size_t pbase = ((size_t)(b * HH + (ty0 + py)) * WW + (tx0 + pxl)) * 256;
            __nv_bfloat16 hh = __float2bfloat16(hn);
            __nv_bfloat16 hl = __float2bfloat16(hn - __bfloat162float(hh));
            *(unsigned short*)(hs + pbase + (g >> 5) * 128 + (g & 31) * 2)      = *(unsigned short*)&hh;
            *(unsigned short*)(hs + pbase + (g >> 5) * 128 + 64 + (g & 31) * 2) = *(unsigned short*)&hl;

            float res = bpv;
#pragma unroll
            for (int ci = 0; ci < 32; ci++) res += xc[p * 32 + ci] * wreg[ci];

            out[(((size_t)(b * TT + tstep) * HH + (ty0 + py)) * WW + (tx0 + pxl)) * FF + g] = hn + res;
        }
    }
}

extern "C" void kernel_launch(void* const* d_in, const int* in_sizes, int n_in,
                              void* d_out, int out_size)
{
    const float* x    = (const float*)d_in[0];
    const float* Wx   = (const float*)d_in[1];
    const float* Wh   = (const float*)d_in[2];
    const float* bias = (const float*)d_in[3];
    const float* Wp   = (const float*)d_in[4];
    const float* bp   = (const float*)d_in[5];
    float* out = (float*)d_out;

    cudaFuncSetAttribute(step_kernel, cudaFuncAttributeMaxDynamicSharedMemorySize, SMEM_BYTES);

    init_state_kernel<<<1024, 256>>>();
    prep_weights_kernel<<<(27 * 16384 + 255) / 256, 256>>>(Wx, Wh);
    convx_kernel<<<16384, 256>>>(x);

    dim3 grid(32, BB);
    for (int t = 0; t < TT; t++)
        step_kernel<<<grid, 256, SMEM_BYTES>>>(x, bias, Wp, bp, out, t);
}